// round 4
// baseline (speedup 1.0000x reference)
#include <cuda_runtime.h>
#include <cstdint>

#define NN 20000
#define NE 320000
#define FN 64
#define FE 16
#define HID 300
#define NDEPTH 3
#define NG 128

#define TM 64
#define TN 64
#define TK 16

// ---------------- static scratch (no runtime allocation allowed) ----------------
__device__ __align__(256) float g_h0[(size_t)NE * HID];
__device__ __align__(256) float g_hA[(size_t)NE * HID];
__device__ __align__(256) float g_hB[(size_t)NE * HID];
__device__ __align__(256) float g_a [(size_t)NN * HID];
__device__ __align__(256) float g_hn[(size_t)NN * HID];
__device__ __align__(256) float g_pool[(size_t)NG * HID];

// ---------------- utility kernels ----------------
__global__ void k_zero(float4* p, int n4) {
    int i = blockIdx.x * blockDim.x + threadIdx.x;
    if (i < n4) p[i] = make_float4(0.f, 0.f, 0.f, 0.f);
}

// segment_sum over edges: a[col[e]] += h[e]
__global__ void k_scatter_edges(const float4* __restrict__ h4,
                                const int* __restrict__ col,
                                float* __restrict__ a) {
    int t = blockIdx.x * blockDim.x + threadIdx.x;
    const int total = NE * (HID / 4);
    if (t >= total) return;
    int e = t / (HID / 4);
    int c = t - e * (HID / 4);
    float4 v = h4[t];
    float* dst = a + (size_t)__ldg(col + e) * HID + (c << 2);
    atomicAdd(dst + 0, v.x);
    atomicAdd(dst + 1, v.y);
    atomicAdd(dst + 2, v.z);
    atomicAdd(dst + 3, v.w);
}

// pooled[batch[n]] += hn[n]
__global__ void k_scatter_pool(const float4* __restrict__ hn4,
                               const int* __restrict__ batch,
                               float* __restrict__ pool) {
    int t = blockIdx.x * blockDim.x + threadIdx.x;
    const int total = NN * (HID / 4);
    if (t >= total) return;
    int n = t / (HID / 4);
    int c = t - n * (HID / 4);
    float4 v = hn4[t];
    float* dst = pool + (size_t)__ldg(batch + n) * HID + (c << 2);
    atomicAdd(dst + 0, v.x);
    atomicAdd(dst + 1, v.y);
    atomicAdd(dst + 2, v.z);
    atomicAdd(dst + 3, v.w);
}

// out[g] = dot(pool[g], Wffn) + b
__global__ void k_ffn(const float* __restrict__ pool, const float* __restrict__ W,
                      const float* __restrict__ b, float* __restrict__ out) {
    __shared__ float red[128];
    int g = blockIdx.x;
    float s = 0.f;
    for (int j = threadIdx.x; j < HID; j += 128)
        s += pool[(size_t)g * HID + j] * W[j];
    red[threadIdx.x] = s;
    __syncthreads();
    for (int k = 64; k > 0; k >>= 1) {
        if (threadIdx.x < k) red[threadIdx.x] += red[threadIdx.x + k];
        __syncthreads();
    }
    if (threadIdx.x == 0) out[g] = red[0] + b[0];
}

// ---------------- GEMM kernels (64x64 tiles, TK=16, 4x4 reg tiles) ----------------

// h0[e] = relu(cat(x[row[e]], edge_attr[e]) @ W_init + b)   K = 80
__global__ void __launch_bounds__(256, 4) k_init(
    const float* __restrict__ x, const float* __restrict__ ea,
    const float* __restrict__ W, const float* __restrict__ bias,
    const int* __restrict__ row, float* __restrict__ out)
{
    __shared__ float As[TM][TK + 1];
    __shared__ float Bs[TK][TN];
    const int eb = blockIdx.y * TM;
    const int jb = blockIdx.x * TN;
    const int tid = threadIdx.x;

    const int lm = tid >> 2;
    const int lk = (tid & 3) << 2;
    const int e_l = eb + lm;
    const float* xp = x  + (size_t)__ldg(row + e_l) * FN;
    const float* ep = ea + (size_t)e_l * FE;

    const int bk = tid >> 4;
    const int bj = (tid & 15) << 2;
    const bool bj_ok = (jb + bj) < HID;

    const int tm = (tid >> 4) << 2;
    const int tn = (tid & 15) << 2;

    float acc[4][4] = {};

    for (int k0 = 0; k0 < FN + FE; k0 += TK) {
        int ka = k0 + lk;  // < 80 always
        float4 av = (ka < FN) ? *(const float4*)(xp + ka)
                              : *(const float4*)(ep + (ka - FN));
        As[lm][lk + 0] = av.x; As[lm][lk + 1] = av.y;
        As[lm][lk + 2] = av.z; As[lm][lk + 3] = av.w;

        int kb = k0 + bk;  // < 80 always
        float4 wv = make_float4(0.f, 0.f, 0.f, 0.f);
        if (bj_ok) wv = *(const float4*)(W + (size_t)kb * HID + jb + bj);
        *(float4*)&Bs[bk][bj] = wv;

        __syncthreads();
#pragma unroll
        for (int k = 0; k < TK; k++) {
            float4 bv = *(const float4*)&Bs[k][tn];
            float a0 = As[tm + 0][k], a1 = As[tm + 1][k];
            float a2 = As[tm + 2][k], a3 = As[tm + 3][k];
            acc[0][0] += a0 * bv.x; acc[0][1] += a0 * bv.y; acc[0][2] += a0 * bv.z; acc[0][3] += a0 * bv.w;
            acc[1][0] += a1 * bv.x; acc[1][1] += a1 * bv.y; acc[1][2] += a1 * bv.z; acc[1][3] += a1 * bv.w;
            acc[2][0] += a2 * bv.x; acc[2][1] += a2 * bv.y; acc[2][2] += a2 * bv.z; acc[2][3] += a2 * bv.w;
            acc[3][0] += a3 * bv.x; acc[3][1] += a3 * bv.y; acc[3][2] += a3 * bv.z; acc[3][3] += a3 * bv.w;
        }
        __syncthreads();
    }

    const int j = jb + tn;
    if (j < HID) {
        float4 bb = *(const float4*)(bias + j);
#pragma unroll
        for (int i = 0; i < 4; i++) {
            int e = eb + tm + i;
            float4 o;
            o.x = fmaxf(acc[i][0] + bb.x, 0.f);
            o.y = fmaxf(acc[i][1] + bb.y, 0.f);
            o.z = fmaxf(acc[i][2] + bb.z, 0.f);
            o.w = fmaxf(acc[i][3] + bb.w, 0.f);
            *(float4*)(out + (size_t)e * HID + j) = o;
        }
    }
}

// hout[e] = relu((a[row[e]] - h[e^1]) @ W + b + h0[e])   K = 300
__global__ void __launch_bounds__(256, 4) k_conv(
    const float* __restrict__ a, const float* __restrict__ h,
    const float* __restrict__ h0, const float* __restrict__ W,
    const float* __restrict__ bias, const int* __restrict__ row,
    float* __restrict__ out)
{
    __shared__ float As[TM][TK + 1];
    __shared__ float Bs[TK][TN];
    const int eb = blockIdx.y * TM;
    const int jb = blockIdx.x * TN;
    const int tid = threadIdx.x;

    const int lm = tid >> 2;
    const int lk = (tid & 3) << 2;
    const int e_l = eb + lm;
    const float* ap = a + (size_t)__ldg(row + e_l) * HID;
    const float* hp = h + (size_t)(e_l ^ 1) * HID;

    const int bk = tid >> 4;
    const int bj = (tid & 15) << 2;
    const bool bj_ok = (jb + bj) < HID;

    const int tm = (tid >> 4) << 2;
    const int tn = (tid & 15) << 2;

    float acc[4][4] = {};

    for (int k0 = 0; k0 < HID; k0 += TK) {
        int ka = k0 + lk;
        float4 av = make_float4(0.f, 0.f, 0.f, 0.f);
        if (ka < HID) {  // HID%4==0, float4 fully in range
            float4 xa = *(const float4*)(ap + ka);
            float4 xh = *(const float4*)(hp + ka);
            av.x = xa.x - xh.x; av.y = xa.y - xh.y;
            av.z = xa.z - xh.z; av.w = xa.w - xh.w;
        }
        As[lm][lk + 0] = av.x; As[lm][lk + 1] = av.y;
        As[lm][lk + 2] = av.z; As[lm][lk + 3] = av.w;

        int kb = k0 + bk;
        float4 wv = make_float4(0.f, 0.f, 0.f, 0.f);
        if (kb < HID && bj_ok) wv = *(const float4*)(W + (size_t)kb * HID + jb + bj);
        *(float4*)&Bs[bk][bj] = wv;

        __syncthreads();
#pragma unroll
        for (int k = 0; k < TK; k++) {
            float4 bv = *(const float4*)&Bs[k][tn];
            float a0 = As[tm + 0][k], a1 = As[tm + 1][k];
            float a2 = As[tm + 2][k], a3 = As[tm + 3][k];
            acc[0][0] += a0 * bv.x; acc[0][1] += a0 * bv.y; acc[0][2] += a0 * bv.z; acc[0][3] += a0 * bv.w;
            acc[1][0] += a1 * bv.x; acc[1][1] += a1 * bv.y; acc[1][2] += a1 * bv.z; acc[1][3] += a1 * bv.w;
            acc[2][0] += a2 * bv.x; acc[2][1] += a2 * bv.y; acc[2][2] += a2 * bv.z; acc[2][3] += a2 * bv.w;
            acc[3][0] += a3 * bv.x; acc[3][1] += a3 * bv.y; acc[3][2] += a3 * bv.z; acc[3][3] += a3 * bv.w;
        }
        __syncthreads();
    }

    const int j = jb + tn;
    if (j < HID) {
        float4 bb = *(const float4*)(bias + j);
#pragma unroll
        for (int i = 0; i < 4; i++) {
            int e = eb + tm + i;
            float4 hv = *(const float4*)(h0 + (size_t)e * HID + j);
            float4 o;
            o.x = fmaxf(acc[i][0] + bb.x + hv.x, 0.f);
            o.y = fmaxf(acc[i][1] + bb.y + hv.y, 0.f);
            o.z = fmaxf(acc[i][2] + bb.z + hv.z, 0.f);
            o.w = fmaxf(acc[i][3] + bb.w + hv.w, 0.f);
            *(float4*)(out + (size_t)e * HID + j) = o;
        }
    }
}

// hn[n] = relu(cat(x[n], s[n]) @ W_e2n + b)   K = 364
__global__ void __launch_bounds__(256, 4) k_e2n(
    const float* __restrict__ x, const float* __restrict__ s,
    const float* __restrict__ W, const float* __restrict__ bias,
    float* __restrict__ out)
{
    __shared__ float As[TM][TK + 1];
    __shared__ float Bs[TK][TN];
    const int nb = blockIdx.y * TM;
    const int jb = blockIdx.x * TN;
    const int tid = threadIdx.x;
    const int KT = FN + HID;  // 364

    const int lm = tid >> 2;
    const int lk = (tid & 3) << 2;
    const int n_l = nb + lm;
    const int n_c = n_l < NN ? n_l : NN - 1;
    const float* xp = x + (size_t)n_c * FN;
    const float* sp = s + (size_t)n_c * HID;

    const int bk = tid >> 4;
    const int bj = (tid & 15) << 2;
    const bool bj_ok = (jb + bj) < HID;

    const int tm = (tid >> 4) << 2;
    const int tn = (tid & 15) << 2;

    float acc[4][4] = {};

    for (int k0 = 0; k0 < KT; k0 += TK) {
        int ka = k0 + lk;
        float4 av = make_float4(0.f, 0.f, 0.f, 0.f);
        if (ka < FN)      av = *(const float4*)(xp + ka);
        else if (ka < KT) av = *(const float4*)(sp + (ka - FN));
        As[lm][lk + 0] = av.x; As[lm][lk + 1] = av.y;
        As[lm][lk + 2] = av.z; As[lm][lk + 3] = av.w;

        int kb = k0 + bk;
        float4 wv = make_float4(0.f, 0.f, 0.f, 0.f);
        if (kb < KT && bj_ok) wv = *(const float4*)(W + (size_t)kb * HID + jb + bj);
        *(float4*)&Bs[bk][bj] = wv;

        __syncthreads();
#pragma unroll
        for (int k = 0; k < TK; k++) {
            float4 bv = *(const float4*)&Bs[k][tn];
            float a0 = As[tm + 0][k], a1 = As[tm + 1][k];
            float a2 = As[tm + 2][k], a3 = As[tm + 3][k];
            acc[0][0] += a0 * bv.x; acc[0][1] += a0 * bv.y; acc[0][2] += a0 * bv.z; acc[0][3] += a0 * bv.w;
            acc[1][0] += a1 * bv.x; acc[1][1] += a1 * bv.y; acc[1][2] += a1 * bv.z; acc[1][3] += a1 * bv.w;
            acc[2][0] += a2 * bv.x; acc[2][1] += a2 * bv.y; acc[2][2] += a2 * bv.z; acc[2][3] += a2 * bv.w;
            acc[3][0] += a3 * bv.x; acc[3][1] += a3 * bv.y; acc[3][2] += a3 * bv.z; acc[3][3] += a3 * bv.w;
        }
        __syncthreads();
    }

    const int j = jb + tn;
    if (j < HID) {
        float4 bb = *(const float4*)(bias + j);
#pragma unroll
        for (int i = 0; i < 4; i++) {
            int n = nb + tm + i;
            if (n >= NN) break;
            float4 o;
            o.x = fmaxf(acc[i][0] + bb.x, 0.f);
            o.y = fmaxf(acc[i][1] + bb.y, 0.f);
            o.z = fmaxf(acc[i][2] + bb.z, 0.f);
            o.w = fmaxf(acc[i][3] + bb.w, 0.f);
            *(float4*)(out + (size_t)n * HID + j) = o;
        }
    }
}

// ---------------- launch ----------------
extern "C" void kernel_launch(void* const* d_in, const int* in_sizes, int n_in,
                              void* d_out, int out_size) {
    const float* x        = (const float*)d_in[0];
    const float* edge_attr= (const float*)d_in[1];
    const int*   edge_idx = (const int*)  d_in[2];
    const int*   batch    = (const int*)  d_in[3];
    const float* W_init   = (const float*)d_in[4];
    const float* b_init   = (const float*)d_in[5];
    const float* W_convs  = (const float*)d_in[6];
    const float* b_convs  = (const float*)d_in[7];
    const float* W_e2n    = (const float*)d_in[8];
    const float* b_e2n    = (const float*)d_in[9];
    const float* W_ffn    = (const float*)d_in[10];
    const float* b_ffn    = (const float*)d_in[11];
    float* out = (float*)d_out;

    const int* row = edge_idx;
    const int* col = edge_idx + NE;

    float *h0, *hA, *hB, *a, *hn, *pool;
    cudaGetSymbolAddress((void**)&h0,   g_h0);
    cudaGetSymbolAddress((void**)&hA,   g_hA);
    cudaGetSymbolAddress((void**)&hB,   g_hB);
    cudaGetSymbolAddress((void**)&a,    g_a);
    cudaGetSymbolAddress((void**)&hn,   g_hn);
    cudaGetSymbolAddress((void**)&pool, g_pool);

    const dim3 gemm_grid((HID + TN - 1) / TN, NE / TM);  // (5, 5000)
    const int a4 = NN * (HID / 4);
    const int e4 = NE * (HID / 4);
    const int p4 = NG * (HID / 4);

    // h0 = relu(edge_init(cat(x[row], edge_attr)))
    k_init<<<gemm_grid, 256>>>(x, edge_attr, W_init, b_init, row, h0);

    const float* hcur = h0;
    float* bufs[2] = {hA, hB};
    for (int l = 0; l < NDEPTH; l++) {
        k_zero<<<(a4 + 255) / 256, 256>>>((float4*)a, a4);
        k_scatter_edges<<<(e4 + 255) / 256, 256>>>((const float4*)hcur, col, a);
        float* hnext = bufs[l & 1];
        k_conv<<<gemm_grid, 256>>>(a, hcur, h0, W_convs + (size_t)l * HID * HID,
                                   b_convs + (size_t)l * HID, row, hnext);
        hcur = hnext;
    }

    // final segment sum -> s (reuse a), node MLP, pooling, FFN
    k_zero<<<(a4 + 255) / 256, 256>>>((float4*)a, a4);
    k_scatter_edges<<<(e4 + 255) / 256, 256>>>((const float4*)hcur, col, a);

    const dim3 e2n_grid((HID + TN - 1) / TN, (NN + TM - 1) / TM);  // (5, 313)
    k_e2n<<<e2n_grid, 256>>>(x, a, W_e2n, b_e2n, hn);

    k_zero<<<(p4 + 255) / 256, 256>>>((float4*)pool, p4);
    k_scatter_pool<<<(a4 + 255) / 256, 256>>>((const float4*)hn, batch, pool);
    k_ffn<<<NG, 128>>>(pool, W_ffn, b_ffn, out);
}

// round 5
// speedup vs baseline: 1.3053x; 1.3053x over previous
#include <cuda_runtime.h>
#include <cuda_bf16.h>
#include <cstdint>

#define NN 20000
#define NE 320000
#define FN 64
#define FE 16
#define HID 300
#define NDEPTH 3
#define NG 128

// SIMT GEMM tiles (init / e2n)
#define TM 64
#define TN 64
#define TK 16

// conv MMA tiles
#define CBM 128
#define CBN 160
#define CBK 32
#define KPAD 320
#define NKB (KPAD / CBK)   // 10
#define ASTR 40            // padded k-stride in halfs (32 + 8)

// ---------------- static scratch (no runtime allocation allowed) ----------------
__device__ __align__(256) float g_h0[(size_t)NE * HID];
__device__ __align__(256) float g_hA[(size_t)NE * HID];
__device__ __align__(256) float g_hB[(size_t)NE * HID];
__device__ __align__(256) float g_a [(size_t)NN * HID];
__device__ __align__(256) float g_hn[(size_t)NN * HID];
__device__ __align__(256) float g_pool[(size_t)NG * HID];
__device__ __align__(256) uint16_t g_WhiT[(size_t)NDEPTH * HID * KPAD];
__device__ __align__(256) uint16_t g_WloT[(size_t)NDEPTH * HID * KPAD];

// ---------------- helpers ----------------
__device__ __forceinline__ uint16_t f2bf_bits(float v) {
    __nv_bfloat16 b = __float2bfloat16(v);
    return *reinterpret_cast<uint16_t*>(&b);
}
__device__ __forceinline__ float bf_bits2f(uint16_t u) {
    __nv_bfloat16 b = *reinterpret_cast<__nv_bfloat16*>(&u);
    return __bfloat162float(b);
}

__device__ __forceinline__ void mma_bf16(float* d, const uint32_t* a,
                                         uint32_t b0, uint32_t b1) {
    asm volatile(
        "mma.sync.aligned.m16n8k16.row.col.f32.bf16.bf16.f32 "
        "{%0,%1,%2,%3}, {%4,%5,%6,%7}, {%8,%9}, {%0,%1,%2,%3};"
        : "+f"(d[0]), "+f"(d[1]), "+f"(d[2]), "+f"(d[3])
        : "r"(a[0]), "r"(a[1]), "r"(a[2]), "r"(a[3]), "r"(b0), "r"(b1));
}

// ---------------- utility kernels ----------------
__global__ void k_zero(float4* p, int n4) {
    int i = blockIdx.x * blockDim.x + threadIdx.x;
    if (i < n4) p[i] = make_float4(0.f, 0.f, 0.f, 0.f);
}

// split W_convs into transposed, K-padded bf16 hi/lo: W_T[l][n][k]
__global__ void k_splitW(const float* __restrict__ W,
                         uint16_t* __restrict__ WhiT, uint16_t* __restrict__ WloT) {
    int idx = blockIdx.x * blockDim.x + threadIdx.x;
    const int total = NDEPTH * HID * KPAD;
    if (idx >= total) return;
    int l = idx / (HID * KPAD);
    int rem = idx - l * (HID * KPAD);
    int n = rem / KPAD;
    int k = rem - n * KPAD;
    float v = (k < HID) ? W[(size_t)l * HID * HID + (size_t)k * HID + n] : 0.f;
    uint16_t hb = f2bf_bits(v);
    float lo = v - bf_bits2f(hb);
    WhiT[idx] = hb;
    WloT[idx] = f2bf_bits(lo);
}

// segment_sum over edges: a[col[e]] += h[e]
__global__ void k_scatter_edges(const float4* __restrict__ h4,
                                const int* __restrict__ col,
                                float* __restrict__ a) {
    int t = blockIdx.x * blockDim.x + threadIdx.x;
    const int total = NE * (HID / 4);
    if (t >= total) return;
    int e = t / (HID / 4);
    int c = t - e * (HID / 4);
    float4 v = h4[t];
    float* dst = a + (size_t)__ldg(col + e) * HID + (c << 2);
    atomicAdd(dst + 0, v.x);
    atomicAdd(dst + 1, v.y);
    atomicAdd(dst + 2, v.z);
    atomicAdd(dst + 3, v.w);
}

// pooled[batch[n]] += hn[n]
__global__ void k_scatter_pool(const float4* __restrict__ hn4,
                               const int* __restrict__ batch,
                               float* __restrict__ pool) {
    int t = blockIdx.x * blockDim.x + threadIdx.x;
    const int total = NN * (HID / 4);
    if (t >= total) return;
    int n = t / (HID / 4);
    int c = t - n * (HID / 4);
    float4 v = hn4[t];
    float* dst = pool + (size_t)__ldg(batch + n) * HID + (c << 2);
    atomicAdd(dst + 0, v.x);
    atomicAdd(dst + 1, v.y);
    atomicAdd(dst + 2, v.z);
    atomicAdd(dst + 3, v.w);
}

__global__ void k_ffn(const float* __restrict__ pool, const float* __restrict__ W,
                      const float* __restrict__ b, float* __restrict__ out) {
    __shared__ float red[128];
    int g = blockIdx.x;
    float s = 0.f;
    for (int j = threadIdx.x; j < HID; j += 128)
        s += pool[(size_t)g * HID + j] * W[j];
    red[threadIdx.x] = s;
    __syncthreads();
    for (int k = 64; k > 0; k >>= 1) {
        if (threadIdx.x < k) red[threadIdx.x] += red[threadIdx.x + k];
        __syncthreads();
    }
    if (threadIdx.x == 0) out[g] = red[0] + b[0];
}

// ---------------- conv layer via tensor cores (split-bf16, 3-MMA) ----------------
// out[e] = relu((a[row[e]] - h[e^1]) @ W + b + h0[e])
__global__ void __launch_bounds__(256, 1) k_conv_mma(
    const float* __restrict__ a, const float* __restrict__ h,
    const float* __restrict__ h0, const uint16_t* __restrict__ WhiT,
    const uint16_t* __restrict__ WloT, const float* __restrict__ bias,
    const int* __restrict__ row, float* __restrict__ out)
{
    __shared__ uint16_t Ah[CBM][ASTR];
    __shared__ uint16_t Al[CBM][ASTR];
    __shared__ uint16_t Bh[CBN][ASTR];
    __shared__ uint16_t Bl[CBN][ASTR];
    __shared__ int rows_s[CBM];

    const int tid = threadIdx.x;
    const int eb = blockIdx.y * CBM;
    const int jb = blockIdx.x * CBN;

    if (tid < CBM) rows_s[tid] = __ldg(row + eb + tid);
    __syncthreads();

    // A staging: thread covers row ai, 16 consecutive k starting at ak0
    const int ai = tid >> 1;
    const int ak0 = (tid & 1) << 4;
    const float* ap = a + (size_t)rows_s[ai] * HID;
    const float* hp = h + (size_t)((eb + ai) ^ 1) * HID;

    // warp/frag mapping
    const int wid = tid >> 5, lane = tid & 31;
    const int wm = wid >> 1, wn = wid & 1;
    const int gp = lane >> 2, tg = lane & 3;

    float acc[2][10][4] = {};
    float rA[16];
    uint32_t rBh[10], rBl[10];

    // ---- prefetch tile 0 into regs ----
#pragma unroll
    for (int v = 0; v < 4; v++) {
        int kg = ak0 + v * 4;  // k0 = 0
        float4 av, hv;
        if (kg < HID) {
            av = *(const float4*)(ap + kg);
            hv = *(const float4*)(hp + kg);
        } else {
            av = make_float4(0.f, 0.f, 0.f, 0.f);
            hv = av;
        }
        rA[v * 4 + 0] = av.x - hv.x; rA[v * 4 + 1] = av.y - hv.y;
        rA[v * 4 + 2] = av.z - hv.z; rA[v * 4 + 3] = av.w - hv.w;
    }
#pragma unroll
    for (int q = 0; q < 10; q++) {
        int idx = tid + 256 * q;
        int n = idx >> 4, kw = idx & 15;
        int ng = jb + n;
        uint32_t vh = 0, vl = 0;
        if (ng < HID) {
            vh = *((const uint32_t*)(WhiT + (size_t)ng * KPAD) + kw);
            vl = *((const uint32_t*)(WloT + (size_t)ng * KPAD) + kw);
        }
        rBh[q] = vh; rBl[q] = vl;
    }

    for (int kb = 0; kb < NKB; kb++) {
        // ---- store staged regs to smem (convert A to split bf16) ----
#pragma unroll
        for (int v = 0; v < 4; v++) {
#pragma unroll
            for (int j = 0; j < 4; j += 2) {
                float v0 = rA[v * 4 + j], v1 = rA[v * 4 + j + 1];
                uint16_t h0b = f2bf_bits(v0);
                uint16_t l0b = f2bf_bits(v0 - bf_bits2f(h0b));
                uint16_t h1b = f2bf_bits(v1);
                uint16_t l1b = f2bf_bits(v1 - bf_bits2f(h1b));
                int kc = ak0 + v * 4 + j;
                *(uint32_t*)&Ah[ai][kc] = (uint32_t)h0b | ((uint32_t)h1b << 16);
                *(uint32_t*)&Al[ai][kc] = (uint32_t)l0b | ((uint32_t)l1b << 16);
            }
        }
#pragma unroll
        for (int q = 0; q < 10; q++) {
            int idx = tid + 256 * q;
            int n = idx >> 4, kw = idx & 15;
            *(uint32_t*)&Bh[n][kw * 2] = rBh[q];
            *(uint32_t*)&Bl[n][kw * 2] = rBl[q];
        }
        __syncthreads();

        // ---- prefetch next tile ----
        if (kb + 1 < NKB) {
            int k0 = (kb + 1) * CBK;
#pragma unroll
            for (int v = 0; v < 4; v++) {
                int kg = k0 + ak0 + v * 4;
                float4 av, hv;
                if (kg < HID) {
                    av = *(const float4*)(ap + kg);
                    hv = *(const float4*)(hp + kg);
                } else {
                    av = make_float4(0.f, 0.f, 0.f, 0.f);
                    hv = av;
                }
                rA[v * 4 + 0] = av.x - hv.x; rA[v * 4 + 1] = av.y - hv.y;
                rA[v * 4 + 2] = av.z - hv.z; rA[v * 4 + 3] = av.w - hv.w;
            }
#pragma unroll
            for (int q = 0; q < 10; q++) {
                int idx = tid + 256 * q;
                int n = idx >> 4, kw = idx & 15;
                int ng = jb + n;
                uint32_t vh = 0, vl = 0;
                if (ng < HID) {
                    vh = *((const uint32_t*)(WhiT + (size_t)ng * KPAD + k0) + kw);
                    vl = *((const uint32_t*)(WloT + (size_t)ng * KPAD + k0) + kw);
                }
                rBh[q] = vh; rBl[q] = vl;
            }
        }

        // ---- compute on current tile ----
#pragma unroll
        for (int kk = 0; kk < CBK; kk += 16) {
            uint32_t ah[2][4], al[2][4];
#pragma unroll
            for (int f = 0; f < 2; f++) {
                int r0 = wm * 32 + f * 16 + gp;
                int c0 = kk + tg * 2;
                ah[f][0] = *(const uint32_t*)&Ah[r0][c0];
                ah[f][1] = *(const uint32_t*)&Ah[r0 + 8][c0];
                ah[f][2] = *(const uint32_t*)&Ah[r0][c0 + 8];
                ah[f][3] = *(const uint32_t*)&Ah[r0 + 8][c0 + 8];
                al[f][0] = *(const uint32_t*)&Al[r0][c0];
                al[f][1] = *(const uint32_t*)&Al[r0 + 8][c0];
                al[f][2] = *(const uint32_t*)&Al[r0][c0 + 8];
                al[f][3] = *(const uint32_t*)&Al[r0 + 8][c0 + 8];
            }
#pragma unroll
            for (int j = 0; j < 10; j++) {
                int n0 = wn * 80 + j * 8 + gp;
                int ck = kk + tg * 2;
                uint32_t bh0 = *(const uint32_t*)&Bh[n0][ck];
                uint32_t bh1 = *(const uint32_t*)&Bh[n0][ck + 8];
                uint32_t bl0 = *(const uint32_t*)&Bl[n0][ck];
                uint32_t bl1 = *(const uint32_t*)&Bl[n0][ck + 8];
#pragma unroll
                for (int f = 0; f < 2; f++) {
                    mma_bf16(acc[f][j], ah[f], bh0, bh1);
                    mma_bf16(acc[f][j], ah[f], bl0, bl1);
                    mma_bf16(acc[f][j], al[f], bh0, bh1);
                }
            }
        }
        __syncthreads();
    }

    // ---- epilogue: + bias + h0 skip, relu, store ----
#pragma unroll
    for (int f = 0; f < 2; f++) {
#pragma unroll
        for (int j = 0; j < 10; j++) {
            int n0 = jb + wn * 80 + j * 8 + tg * 2;
            if (n0 >= HID) continue;
            float2 bb = *(const float2*)(bias + n0);
#pragma unroll
            for (int half = 0; half < 2; half++) {
                int e = eb + wm * 32 + f * 16 + gp + half * 8;
                float2 hz = *(const float2*)(h0 + (size_t)e * HID + n0);
                float o0 = acc[f][j][half * 2 + 0] + bb.x + hz.x;
                float o1 = acc[f][j][half * 2 + 1] + bb.y + hz.y;
                float2 o = make_float2(fmaxf(o0, 0.f), fmaxf(o1, 0.f));
                *(float2*)(out + (size_t)e * HID + n0) = o;
            }
        }
    }
}

// ---------------- SIMT GEMMs (init, e2n) ----------------

// h0[e] = relu(cat(x[row[e]], edge_attr[e]) @ W_init + b)   K = 80
__global__ void __launch_bounds__(256, 4) k_init(
    const float* __restrict__ x, const float* __restrict__ ea,
    const float* __restrict__ W, const float* __restrict__ bias,
    const int* __restrict__ row, float* __restrict__ out)
{
    __shared__ float As[TM][TK + 1];
    __shared__ float Bs[TK][TN];
    const int eb = blockIdx.y * TM;
    const int jb = blockIdx.x * TN;
    const int tid = threadIdx.x;

    const int lm = tid >> 2;
    const int lk = (tid & 3) << 2;
    const int e_l = eb + lm;
    const float* xp = x  + (size_t)__ldg(row + e_l) * FN;
    const float* ep = ea + (size_t)e_l * FE;

    const int bk = tid >> 4;
    const int bj = (tid & 15) << 2;
    const bool bj_ok = (jb + bj) < HID;

    const int tm = (tid >> 4) << 2;
    const int tn = (tid & 15) << 2;

    float acc[4][4] = {};

    for (int k0 = 0; k0 < FN + FE; k0 += TK) {
        int ka = k0 + lk;
        float4 av = (ka < FN) ? *(const float4*)(xp + ka)
                              : *(const float4*)(ep + (ka - FN));
        As[lm][lk + 0] = av.x; As[lm][lk + 1] = av.y;
        As[lm][lk + 2] = av.z; As[lm][lk + 3] = av.w;

        int kb = k0 + bk;
        float4 wv = make_float4(0.f, 0.f, 0.f, 0.f);
        if (bj_ok) wv = *(const float4*)(W + (size_t)kb * HID + jb + bj);
        *(float4*)&Bs[bk][bj] = wv;

        __syncthreads();
#pragma unroll
        for (int k = 0; k < TK; k++) {
            float4 bv = *(const float4*)&Bs[k][tn];
            float a0 = As[tm + 0][k], a1 = As[tm + 1][k];
            float a2 = As[tm + 2][k], a3 = As[tm + 3][k];
            acc[0][0] += a0 * bv.x; acc[0][1] += a0 * bv.y; acc[0][2] += a0 * bv.z; acc[0][3] += a0 * bv.w;
            acc[1][0] += a1 * bv.x; acc[1][1] += a1 * bv.y; acc[1][2] += a1 * bv.z; acc[1][3] += a1 * bv.w;
            acc[2][0] += a2 * bv.x; acc[2][1] += a2 * bv.y; acc[2][2] += a2 * bv.z; acc[2][3] += a2 * bv.w;
            acc[3][0] += a3 * bv.x; acc[3][1] += a3 * bv.y; acc[3][2] += a3 * bv.z; acc[3][3] += a3 * bv.w;
        }
        __syncthreads();
    }

    const int j = jb + tn;
    if (j < HID) {
        float4 bb = *(const float4*)(bias + j);
#pragma unroll
        for (int i = 0; i < 4; i++) {
            int e = eb + tm + i;
            float4 o;
            o.x = fmaxf(acc[i][0] + bb.x, 0.f);
            o.y = fmaxf(acc[i][1] + bb.y, 0.f);
            o.z = fmaxf(acc[i][2] + bb.z, 0.f);
            o.w = fmaxf(acc[i][3] + bb.w, 0.f);
            *(float4*)(out + (size_t)e * HID + j) = o;
        }
    }
}

// hn[n] = relu(cat(x[n], s[n]) @ W_e2n + b)   K = 364
__global__ void __launch_bounds__(256, 4) k_e2n(
    const float* __restrict__ x, const float* __restrict__ s,
    const float* __restrict__ W, const float* __restrict__ bias,
    float* __restrict__ out)
{
    __shared__ float As[TM][TK + 1];
    __shared__ float Bs[TK][TN];
    const int nb = blockIdx.y * TM;
    const int jb = blockIdx.x * TN;
    const int tid = threadIdx.x;
    const int KT = FN + HID;

    const int lm = tid >> 2;
    const int lk = (tid & 3) << 2;
    const int n_l = nb + lm;
    const int n_c = n_l < NN ? n_l : NN - 1;
    const float* xp = x + (size_t)n_c * FN;
    const float* sp = s + (size_t)n_c * HID;

    const int bk = tid >> 4;
    const int bj = (tid & 15) << 2;
    const bool bj_ok = (jb + bj) < HID;

    const int tm = (tid >> 4) << 2;
    const int tn = (tid & 15) << 2;

    float acc[4][4] = {};

    for (int k0 = 0; k0 < KT; k0 += TK) {
        int ka = k0 + lk;
        float4 av = make_float4(0.f, 0.f, 0.f, 0.f);
        if (ka < FN)      av = *(const float4*)(xp + ka);
        else if (ka < KT) av = *(const float4*)(sp + (ka - FN));
        As[lm][lk + 0] = av.x; As[lm][lk + 1] = av.y;
        As[lm][lk + 2] = av.z; As[lm][lk + 3] = av.w;

        int kb = k0 + bk;
        float4 wv = make_float4(0.f, 0.f, 0.f, 0.f);
        if (kb < KT && bj_ok) wv = *(const float4*)(W + (size_t)kb * HID + jb + bj);
        *(float4*)&Bs[bk][bj] = wv;

        __syncthreads();
#pragma unroll
        for (int k = 0; k < TK; k++) {
            float4 bv = *(const float4*)&Bs[k][tn];
            float a0 = As[tm + 0][k], a1 = As[tm + 1][k];
            float a2 = As[tm + 2][k], a3 = As[tm + 3][k];
            acc[0][0] += a0 * bv.x; acc[0][1] += a0 * bv.y; acc[0][2] += a0 * bv.z; acc[0][3] += a0 * bv.w;
            acc[1][0] += a1 * bv.x; acc[1][1] += a1 * bv.y; acc[1][2] += a1 * bv.z; acc[1][3] += a1 * bv.w;
            acc[2][0] += a2 * bv.x; acc[2][1] += a2 * bv.y; acc[2][2] += a2 * bv.z; acc[2][3] += a2 * bv.w;
            acc[3][0] += a3 * bv.x; acc[3][1] += a3 * bv.y; acc[3][2] += a3 * bv.z; acc[3][3] += a3 * bv.w;
        }
        __syncthreads();
    }

    const int j = jb + tn;
    if (j < HID) {
        float4 bb = *(const float4*)(bias + j);
#pragma unroll
        for (int i = 0; i < 4; i++) {
            int n = nb + tm + i;
            if (n >= NN) break;
            float4 o;
            o.x = fmaxf(acc[i][0] + bb.x, 0.f);
            o.y = fmaxf(acc[i][1] + bb.y, 0.f);
            o.z = fmaxf(acc[i][2] + bb.z, 0.f);
            o.w = fmaxf(acc[i][3] + bb.w, 0.f);
            *(float4*)(out + (size_t)n * HID + j) = o;
        }
    }
}

// ---------------- launch ----------------
extern "C" void kernel_launch(void* const* d_in, const int* in_sizes, int n_in,
                              void* d_out, int out_size) {
    const float* x        = (const float*)d_in[0];
    const float* edge_attr= (const float*)d_in[1];
    const int*   edge_idx = (const int*)  d_in[2];
    const int*   batch    = (const int*)  d_in[3];
    const float* W_init   = (const float*)d_in[4];
    const float* b_init   = (const float*)d_in[5];
    const float* W_convs  = (const float*)d_in[6];
    const float* b_convs  = (const float*)d_in[7];
    const float* W_e2n    = (const float*)d_in[8];
    const float* b_e2n    = (const float*)d_in[9];
    const float* W_ffn    = (const float*)d_in[10];
    const float* b_ffn    = (const float*)d_in[11];
    float* out = (float*)d_out;

    const int* row = edge_idx;
    const int* col = edge_idx + NE;

    float *h0, *hA, *hB, *a, *hn, *pool;
    uint16_t *WhiT, *WloT;
    cudaGetSymbolAddress((void**)&h0,   g_h0);
    cudaGetSymbolAddress((void**)&hA,   g_hA);
    cudaGetSymbolAddress((void**)&hB,   g_hB);
    cudaGetSymbolAddress((void**)&a,    g_a);
    cudaGetSymbolAddress((void**)&hn,   g_hn);
    cudaGetSymbolAddress((void**)&pool, g_pool);
    cudaGetSymbolAddress((void**)&WhiT, g_WhiT);
    cudaGetSymbolAddress((void**)&WloT, g_WloT);

    const int a4 = NN * (HID / 4);
    const int e4 = NE * (HID / 4);
    const int p4 = NG * (HID / 4);

    // split conv weights (bf16 hi/lo, transposed [n][k], K padded to 320)
    const int wtot = NDEPTH * HID * KPAD;
    k_splitW<<<(wtot + 255) / 256, 256>>>(W_convs, WhiT, WloT);

    // h0 = relu(edge_init(cat(x[row], edge_attr)))
    const dim3 init_grid((HID + TN - 1) / TN, NE / TM);
    k_init<<<init_grid, 256>>>(x, edge_attr, W_init, b_init, row, h0);

    const dim3 conv_grid(2, NE / CBM);  // (2, 2500)
    const float* hcur = h0;
    float* bufs[2] = {hA, hB};
    for (int l = 0; l < NDEPTH; l++) {
        k_zero<<<(a4 + 255) / 256, 256>>>((float4*)a, a4);
        k_scatter_edges<<<(e4 + 255) / 256, 256>>>((const float4*)hcur, col, a);
        float* hnext = bufs[l & 1];
        k_conv_mma<<<conv_grid, 256>>>(a, hcur, h0,
                                       WhiT + (size_t)l * HID * KPAD,
                                       WloT + (size_t)l * HID * KPAD,
                                       b_convs + (size_t)l * HID, row, hnext);
        hcur = hnext;
    }

    // final segment sum -> s (reuse a), node MLP, pooling, FFN
    k_zero<<<(a4 + 255) / 256, 256>>>((float4*)a, a4);
    k_scatter_edges<<<(e4 + 255) / 256, 256>>>((const float4*)hcur, col, a);

    const dim3 e2n_grid((HID + TN - 1) / TN, (NN + TM - 1) / TM);
    k_e2n<<<e2n_grid, 256>>>(x, a, W_e2n, b_e2n, hn);

    k_zero<<<(p4 + 255) / 256, 256>>>((float4*)pool, p4);
    k_scatter_pool<<<(a4 + 255) / 256, 256>>>((const float4*)hn, batch, pool);
    k_ffn<<<NG, 128>>>(pool, W_ffn, b_ffn, out);
}